// round 13
// baseline (speedup 1.0000x reference)
#include <cuda_runtime.h>
#include <cstdint>

#define BB   32
#define CIN  256
#define HH   56
#define WWD  56
#define COUT 256
#define NK   4
#define HID  64

#define CIC   16            // ci per stage
#define NSTG  (CIN/CIC)     // 16
#define NROWS 4             // output rows per CTA
#define NTAP  (NSTG*9)      // 144

// -------- scratch (device globals) --------
__device__ float g_v[BB*CIN];
__device__ float g_a[BB*NK];
// mixed weights (tf32), fragment-permuted:
// [b][tap][ct(4)][stage(16)][co_t(4)][kk(2)][lane(32)][v(4)]
__device__ __align__(16) float g_wa[(size_t)BB*9*COUT*CIN];
// pre-transposed x (tf32, halo-padded, ci-permuted, XOR-swizzled): [b][stage][hp(58)][iw(58)][16]
__device__ __align__(16) float g_xt[(size_t)BB*NSTG*58*58*CIC];

// ===================== helpers =====================
__device__ __forceinline__ uint32_t smem_u32(const void* p) {
    uint32_t a;
    asm("{ .reg .u64 t; cvta.to.shared.u64 t, %1; cvt.u32.u64 %0, t; }" : "=r"(a) : "l"(p));
    return a;
}
__device__ __forceinline__ uint32_t f2tf32(float f) {
    uint32_t r;
    asm("cvt.rna.tf32.f32 %0, %1;" : "=r"(r) : "f"(f));
    return r;
}
__device__ __forceinline__ void mma_tf32(float* c, const uint32_t* a, const uint32_t* b) {
    asm volatile("mma.sync.aligned.m16n8k8.row.col.f32.tf32.tf32.f32 "
        "{%0,%1,%2,%3}, {%4,%5,%6,%7}, {%8,%9}, {%0,%1,%2,%3};"
        : "+f"(c[0]), "+f"(c[1]), "+f"(c[2]), "+f"(c[3])
        : "r"(a[0]), "r"(a[1]), "r"(a[2]), "r"(a[3]), "r"(b[0]), "r"(b[1]));
}
#define CP_ASYNC16(dst, src) \
    asm volatile("cp.async.ca.shared.global [%0], [%1], 16;" :: "r"(dst), "l"(src) : "memory")
#define CP_COMMIT() asm volatile("cp.async.commit_group;" ::: "memory")
#define CP_WAIT0()  asm volatile("cp.async.wait_group 0;" ::: "memory")
#define CP_WAIT1()  asm volatile("cp.async.wait_group 1;" ::: "memory")

#define LDSV4(r0,r1,r2,r3,a) \
    asm volatile("ld.shared.v4.u32 {%0,%1,%2,%3}, [%4];" : "=r"(r0),"=r"(r1),"=r"(r2),"=r"(r3) : "r"(a))
#define LDSV2(r0,r1,a) \
    asm volatile("ld.shared.v2.u32 {%0,%1}, [%2];" : "=r"(r0),"=r"(r1) : "r"(a))

// ===================== 1) global average pool =====================
__global__ void gap_kernel(const float* __restrict__ x) {
    int bc = blockIdx.x;
    const float* p = x + (size_t)bc * (HH*WWD);
    float s = 0.f;
    for (int i = threadIdx.x; i < HH*WWD; i += 256) s += p[i];
    __shared__ float red[256];
    red[threadIdx.x] = s;
    __syncthreads();
    for (int off = 128; off > 0; off >>= 1) {
        if (threadIdx.x < off) red[threadIdx.x] += red[threadIdx.x + off];
        __syncthreads();
    }
    if (threadIdx.x == 0) g_v[bc] = red[0] * (1.0f / (HH*WWD));
}

// ===================== 2) router MLP + softmax =====================
__global__ void router_kernel(const float* __restrict__ fc1w, const float* __restrict__ fc1b,
                              const float* __restrict__ fc2w, const float* __restrict__ fc2b) {
    int b = blockIdx.x;
    __shared__ float sv[CIN];
    __shared__ float sh[HID];
    __shared__ float sl[NK];
    for (int i = threadIdx.x; i < CIN; i += 64) sv[i] = g_v[b*CIN + i];
    __syncthreads();
    int j = threadIdx.x;
    float acc = fc1b[j];
    for (int c = 0; c < CIN; c++) acc += sv[c] * fc1w[j*CIN + c];
    sh[j] = acc > 0.f ? acc : 0.f;
    __syncthreads();
    if (j < NK) {
        float l = fc2b[j];
        for (int t = 0; t < HID; t++) l += sh[t] * fc2w[j*HID + t];
        sl[j] = l;
    }
    __syncthreads();
    if (j == 0) {
        float m = sl[0];
        for (int k = 1; k < NK; k++) m = fmaxf(m, sl[k]);
        float e[NK], ssum = 0.f;
        for (int k = 0; k < NK; k++) { e[k] = expf(sl[k] - m); ssum += e[k]; }
        float inv = 1.0f / ssum;
        for (int k = 0; k < NK; k++) g_a[b*NK + k] = e[k] * inv;
    }
}

// ===================== 2b) x transpose -> g_xt (tf32, padded, permuted, swizzled) =====================
// grid (58 hp, 16 stage, 32 b), 128 threads.
__global__ void xpose_kernel(const float* __restrict__ x) {
    int hp = blockIdx.x, sg = blockIdx.y, b = blockIdx.z;
    float* orow = g_xt + ((size_t)(b*NSTG + sg)*58 + hp) * (58*CIC);
    int tid = threadIdx.x;
    if (hp == 0 || hp == 57) {
        for (int u = tid; u < 58*CIC; u += 128) orow[u] = 0.f;
        return;
    }
    __shared__ float tile[CIC][57];
    int h = hp - 1;
    for (int u = tid; u < CIC*WWD; u += 128) {
        int ci = u / WWD, w = u - ci*WWD;
        tile[ci][w] = x[((size_t)(b*CIN + sg*CIC + ci)*HH + h)*WWD + w];
    }
    __syncthreads();
    for (int u = tid; u < 58*CIC; u += 128) {
        int iw = u >> 4, pp = u & 15;
        float v = 0.f;
        if (iw >= 1 && iw <= 56) {
            int ci = (pp & 8) | ((pp & 1) << 2) | ((pp >> 1) & 3);   // inverse perm
            v = tile[ci][iw - 1];
        }
        // XOR swizzle: halves of the 16-word group swapped for iw with bit1 set
        orow[(iw << 4) | (pp ^ ((iw & 2) << 2))] = __uint_as_float(f2tf32(v));
    }
}

// ===================== 3) mix banks -> fragment-permuted g_wa (tf32) =====================
// grid (COUT, 4): each block handles 8 samples; banks held in smem.
__global__ void mix_kernel(const float* __restrict__ wb) {
    __shared__ float s[NK][CIN*9];
    __shared__ float sa[BB*NK];
    int co = blockIdx.x, b0 = blockIdx.y * 8;
    for (int idx = threadIdx.x; idx < NK*CIN*9; idx += 256) {
        int k = idx / (CIN*9);
        int jj = idx - k * (CIN*9);
        s[k][jj] = wb[((size_t)k*COUT + co)*(CIN*9) + jj];
    }
    if (threadIdx.x < BB*NK) sa[threadIdx.x] = g_a[threadIdx.x];
    int ct = co >> 6, co_t = (co >> 4) & 3, r = co & 15;
    __syncthreads();
    for (int bi = 0; bi < 8; bi++) {
        int b = b0 + bi;
        float a0 = sa[b*NK+0], a1 = sa[b*NK+1], a2 = sa[b*NK+2], a3 = sa[b*NK+3];
        for (int idx = threadIdx.x; idx < 9*CIN; idx += 256) {
            int tap = idx >> 8;
            int ci  = idx & 255;
            int src = ci*9 + tap;
            float v = a0*s[0][src] + a1*s[1][src] + a2*s[2][src] + a3*s[3][src];
            int stage = ci >> 4, k_t = (ci >> 3) & 1, cc = ci & 7;
            int lane = (r & 7)*4 + (cc & 3);
            int vv   = ((r >> 3) & 1) + 2*((cc >> 2) & 1);
            size_t dst = ((((((((size_t)b*9 + tap)*4 + ct)*NSTG + stage)*4 + co_t)*2 + k_t)*32 + lane)*4) + vv;
            g_wa[dst] = __uint_as_float(f2tf32(v));
        }
    }
}

// ===================== 4) conv: tf32 mma.sync, depth-2 async pipeline =====================
// grid (14 row-quads, 4 co-quarters, 32 b), 128 threads (4 warps), 3 CTAs/SM.
// sx: 2 buffers, packed+swizzled (22.3KB each). A: 3 buffers (4KB each).
// Tap g issues {A(g+2), sx chunk}; waits wait_group(1) -> A(g+1) landed (issued a full tap ago).

#define SXB_BYTES  (6*58*64)                // 22272 per buffer
#define SAB_BYTES  4096                     // per A buffer
#define SX_SLOTS   (6*58*4)                 // 1392 16B slots per sx buffer
#define SX_CHUNK   (SX_SLOTS/8)             // 174 slots per tap
#define SMEM_SZ    (2*SXB_BYTES + 3*SAB_BYTES)   // 56832 B

__global__ void __launch_bounds__(128, 3)
conv_kernel(float* __restrict__ out) {
    extern __shared__ float smem[];
    uint32_t sxaddr = smem_u32(smem);
    uint32_t saddrA = sxaddr + 2*SXB_BYTES;

    int tid = threadIdx.x, lane = tid & 31;
    int lane4 = lane & 3, laneq = lane >> 2;
    int nt4 = blockIdx.x, ct = blockIdx.y, b = blockIdx.z;
    int h0 = nt4 * NROWS;
    int orow = tid >> 5;                     // warp = output row 0..3

    uint32_t aLane = saddrA + (uint32_t)(lane * 16);

    float c[4][7][4];
    #pragma unroll
    for (int i = 0; i < 4; i++)
        #pragma unroll
        for (int j = 0; j < 7; j++)
            #pragma unroll
            for (int q = 0; q < 4; q++) c[i][j][q] = 0.f;

    // prologue: group0 = {sx(0), A(0)}, group1 = {A(1)}
    {
        const float4* xsrc = (const float4*)(g_xt + ((size_t)(b*NSTG + 0)*58 + h0) * (58*CIC));
        for (int u = tid; u < SX_SLOTS; u += 128)
            CP_ASYNC16(sxaddr + (uint32_t)(u*16), xsrc + u);
        const float* asrc = g_wa + ((((size_t)b*9 + 0)*4 + ct)*NSTG + 0) * (size_t)(SAB_BYTES/4);
        #pragma unroll
        for (int it = 0; it < 2; it++) {
            int u = it*128 + tid;
            CP_ASYNC16(saddrA + (uint32_t)(u*16), asrc + u*4);
        }
        CP_COMMIT();
        const float* asrc1 = g_wa + ((((size_t)b*9 + 1)*4 + ct)*NSTG + 0) * (size_t)(SAB_BYTES/4);
        #pragma unroll
        for (int it = 0; it < 2; it++) {
            int u = it*128 + tid;
            CP_ASYNC16(saddrA + (uint32_t)(SAB_BYTES + u*16), asrc1 + u*4);
        }
        CP_COMMIT();
        CP_WAIT0();
        __syncthreads();
    }

    int abuf = 0, pfbuf = 2;                 // compute buffer for g, prefetch buffer for g+2

    for (int s = 0; s < NSTG; s++) {
        for (int t = 0; t < 9; t++) {
            int g = s*9 + t;
            bool issued = (g + 2 < NTAP);
            // ---- issue async group: A(g+2) + sx chunk t of stage s+1
            if (issued) {
                int gn = g + 2;
                int sn = gn / 9, tn = gn - sn*9;
                const float* asrc = g_wa + ((((size_t)b*9 + tn)*4 + ct)*NSTG + sn) * (size_t)(SAB_BYTES/4);
                uint32_t adst = saddrA + (uint32_t)(pfbuf * SAB_BYTES);
                #pragma unroll
                for (int it = 0; it < 2; it++) {
                    int u = it*128 + tid;
                    CP_ASYNC16(adst + (uint32_t)(u*16), asrc + u*4);
                }
                if (t < 8 && s + 1 < NSTG) {
                    const float4* xsrc = (const float4*)(g_xt + ((size_t)(b*NSTG + s+1)*58 + h0) * (58*CIC));
                    uint32_t xdst = sxaddr + (uint32_t)(((s+1) & 1) * SXB_BYTES);
                    int u0 = t*SX_CHUNK + tid;
                    CP_ASYNC16(xdst + (uint32_t)(u0*16), xsrc + u0);
                    int u1 = u0 + 128;
                    if (tid < SX_CHUNK - 128)
                        CP_ASYNC16(xdst + (uint32_t)(u1*16), xsrc + u1);
                }
                CP_COMMIT();
            }

            // ---- compute tap g
            int dy = t / 3, dx = t - dy * 3;
            int hb = ((dx + laneq) & 2) << 4;        // 0 or 32 bytes (XOR-swizzle half select)
            uint32_t sxw = sxaddr + (uint32_t)((s & 1) * SXB_BYTES)
                         + (uint32_t)((((orow + dy)*58 + dx + laneq) * 64) + lane4*8);
            uint32_t sxk0 = sxw + (uint32_t)hb;          // kk=0: word 0 ^ h
            uint32_t sxk1 = sxw + (uint32_t)(32 ^ hb);   // kk=1: word 8 ^ h
            uint32_t sAb = aLane + (uint32_t)(abuf * SAB_BYTES);

            #pragma unroll
            for (int kk = 0; kk < 2; kk++) {
                uint32_t a[4][4];
                #pragma unroll
                for (int mt = 0; mt < 4; mt++)
                    LDSV4(a[mt][0], a[mt][1], a[mt][2], a[mt][3],
                          sAb + (uint32_t)((mt*2 + kk)*512));
                uint32_t bbase = kk ? sxk1 : sxk0;
                #pragma unroll
                for (int nt = 0; nt < 7; nt++) {
                    uint32_t bf[2];
                    LDSV2(bf[0], bf[1], bbase + (uint32_t)(nt*512));
                    mma_tf32(c[0][nt], a[0], bf);
                    mma_tf32(c[1][nt], a[1], bf);
                    mma_tf32(c[2][nt], a[2], bf);
                    mma_tf32(c[3][nt], a[3], bf);
                }
            }

            if (g + 1 < NTAP) {
                if (issued) { CP_WAIT1(); } else { CP_WAIT0(); }
                __syncthreads();
            }
            abuf = (abuf == 2) ? 0 : abuf + 1;
            pfbuf = (pfbuf == 2) ? 0 : pfbuf + 1;
        }
    }

    // ---- epilogue: float2 stores
    int h = h0 + orow;
    #pragma unroll
    for (int mt = 0; mt < 4; mt++) {
        int co_base = ct*64 + mt*16 + laneq;
        #pragma unroll
        for (int half = 0; half < 2; half++) {
            int co = co_base + half*8;
            float* plane = out + ((size_t)(b*COUT + co)*HH + h)*WWD;
            #pragma unroll
            for (int nt = 0; nt < 7; nt++) {
                int wcol = nt*8 + lane4*2;
                *(float2*)(plane + wcol) = make_float2(c[mt][nt][half*2], c[mt][nt][half*2 + 1]);
            }
        }
    }
}

// ===================== launch =====================
extern "C" void kernel_launch(void* const* d_in, const int* in_sizes, int n_in,
                              void* d_out, int out_size) {
    const float* x    = (const float*)d_in[0];
    const float* wb   = (const float*)d_in[1];
    const float* fc1w = (const float*)d_in[2];
    const float* fc1b = (const float*)d_in[3];
    const float* fc2w = (const float*)d_in[4];
    const float* fc2b = (const float*)d_in[5];
    float* out = (float*)d_out;

    cudaFuncSetAttribute(conv_kernel, cudaFuncAttributeMaxDynamicSharedMemorySize, SMEM_SZ);
    cudaFuncSetAttribute(conv_kernel, cudaFuncAttributePreferredSharedMemoryCarveout,
                         cudaSharedmemCarveoutMaxShared);

    gap_kernel<<<BB*CIN, 256>>>(x);
    router_kernel<<<BB, 64>>>(fc1w, fc1b, fc2w, fc2b);
    xpose_kernel<<<dim3(58, NSTG, BB), 128>>>(x);
    mix_kernel<<<dim3(COUT, 4), 256>>>(wb);
    conv_kernel<<<dim3(HH/NROWS, 4, BB), 128, SMEM_SZ>>>(out);
}

// round 14
// speedup vs baseline: 1.0823x; 1.0823x over previous
#include <cuda_runtime.h>
#include <cstdint>

#define BB   32
#define CIN  256
#define HH   56
#define WWD  56
#define COUT 256
#define NK   4
#define HID  64

#define CIC   16            // ci per stage
#define NSTG  (CIN/CIC)     // 16
#define NROWS 4             // output rows per CTA
#define NRS   (NSTG*3)      // 48 row-steps

// -------- scratch (device globals) --------
__device__ float g_v[BB*CIN];
__device__ float g_a[BB*NK];
// mixed weights (tf32), row-step grouped + fragment-permuted:
// [b][ct(4)][stage(16)][dy(3)][dx(3)][co_t(4)][kk(2)][lane(32)][v(4)]
__device__ __align__(16) float g_wa[(size_t)BB*9*COUT*CIN];
// pre-transposed x (tf32, halo-padded, ci-permuted, XOR-swizzled): [b][stage][hp(58)][iw(58)][16]
__device__ __align__(16) float g_xt[(size_t)BB*NSTG*58*58*CIC];

// ===================== helpers =====================
__device__ __forceinline__ uint32_t smem_u32(const void* p) {
    uint32_t a;
    asm("{ .reg .u64 t; cvta.to.shared.u64 t, %1; cvt.u32.u64 %0, t; }" : "=r"(a) : "l"(p));
    return a;
}
__device__ __forceinline__ uint32_t f2tf32(float f) {
    uint32_t r;
    asm("cvt.rna.tf32.f32 %0, %1;" : "=r"(r) : "f"(f));
    return r;
}
__device__ __forceinline__ void mma_tf32(float* c, const uint32_t* a, const uint32_t* b) {
    asm volatile("mma.sync.aligned.m16n8k8.row.col.f32.tf32.tf32.f32 "
        "{%0,%1,%2,%3}, {%4,%5,%6,%7}, {%8,%9}, {%0,%1,%2,%3};"
        : "+f"(c[0]), "+f"(c[1]), "+f"(c[2]), "+f"(c[3])
        : "r"(a[0]), "r"(a[1]), "r"(a[2]), "r"(a[3]), "r"(b[0]), "r"(b[1]));
}
#define CP_ASYNC16(dst, src) \
    asm volatile("cp.async.ca.shared.global [%0], [%1], 16;" :: "r"(dst), "l"(src) : "memory")
#define CP_COMMIT() asm volatile("cp.async.commit_group;" ::: "memory")
#define CP_WAIT0()  asm volatile("cp.async.wait_group 0;" ::: "memory")

#define LDSV4(r0,r1,r2,r3,a) \
    asm volatile("ld.shared.v4.u32 {%0,%1,%2,%3}, [%4];" : "=r"(r0),"=r"(r1),"=r"(r2),"=r"(r3) : "r"(a))
#define LDSV2(r0,r1,a) \
    asm volatile("ld.shared.v2.u32 {%0,%1}, [%2];" : "=r"(r0),"=r"(r1) : "r"(a))

// ===================== 1) global average pool =====================
__global__ void gap_kernel(const float* __restrict__ x) {
    int bc = blockIdx.x;
    const float* p = x + (size_t)bc * (HH*WWD);
    float s = 0.f;
    for (int i = threadIdx.x; i < HH*WWD; i += 256) s += p[i];
    __shared__ float red[256];
    red[threadIdx.x] = s;
    __syncthreads();
    for (int off = 128; off > 0; off >>= 1) {
        if (threadIdx.x < off) red[threadIdx.x] += red[threadIdx.x + off];
        __syncthreads();
    }
    if (threadIdx.x == 0) g_v[bc] = red[0] * (1.0f / (HH*WWD));
}

// ===================== 2) router MLP + softmax =====================
__global__ void router_kernel(const float* __restrict__ fc1w, const float* __restrict__ fc1b,
                              const float* __restrict__ fc2w, const float* __restrict__ fc2b) {
    int b = blockIdx.x;
    __shared__ float sv[CIN];
    __shared__ float sh[HID];
    __shared__ float sl[NK];
    for (int i = threadIdx.x; i < CIN; i += 64) sv[i] = g_v[b*CIN + i];
    __syncthreads();
    int j = threadIdx.x;
    float acc = fc1b[j];
    for (int c = 0; c < CIN; c++) acc += sv[c] * fc1w[j*CIN + c];
    sh[j] = acc > 0.f ? acc : 0.f;
    __syncthreads();
    if (j < NK) {
        float l = fc2b[j];
        for (int t = 0; t < HID; t++) l += sh[t] * fc2w[j*HID + t];
        sl[j] = l;
    }
    __syncthreads();
    if (j == 0) {
        float m = sl[0];
        for (int k = 1; k < NK; k++) m = fmaxf(m, sl[k]);
        float e[NK], ssum = 0.f;
        for (int k = 0; k < NK; k++) { e[k] = expf(sl[k] - m); ssum += e[k]; }
        float inv = 1.0f / ssum;
        for (int k = 0; k < NK; k++) g_a[b*NK + k] = e[k] * inv;
    }
}

// ===================== 2b) x transpose -> g_xt (tf32, padded, permuted, swizzled) =====================
// grid (58 hp, 16 stage, 32 b), 128 threads.
__global__ void xpose_kernel(const float* __restrict__ x) {
    int hp = blockIdx.x, sg = blockIdx.y, b = blockIdx.z;
    float* orow = g_xt + ((size_t)(b*NSTG + sg)*58 + hp) * (58*CIC);
    int tid = threadIdx.x;
    if (hp == 0 || hp == 57) {
        for (int u = tid; u < 58*CIC; u += 128) orow[u] = 0.f;
        return;
    }
    __shared__ float tile[CIC][57];
    int h = hp - 1;
    for (int u = tid; u < CIC*WWD; u += 128) {
        int ci = u / WWD, w = u - ci*WWD;
        tile[ci][w] = x[((size_t)(b*CIN + sg*CIC + ci)*HH + h)*WWD + w];
    }
    __syncthreads();
    for (int u = tid; u < 58*CIC; u += 128) {
        int iw = u >> 4, pp = u & 15;
        float v = 0.f;
        if (iw >= 1 && iw <= 56) {
            int ci = (pp & 8) | ((pp & 1) << 2) | ((pp >> 1) & 3);   // inverse perm
            v = tile[ci][iw - 1];
        }
        // XOR swizzle: halves of the 16-word group swapped for iw with bit1 set
        orow[(iw << 4) | (pp ^ ((iw & 2) << 2))] = __uint_as_float(f2tf32(v));
    }
}

// ===================== 3) mix banks -> row-step-grouped g_wa (tf32) =====================
// one block per co; all 32 samples with banks held in smem (wb read ONCE).
__global__ void mix_kernel(const float* __restrict__ wb) {
    __shared__ float s[NK][CIN*9];
    __shared__ float sa[BB*NK];
    int co = blockIdx.x;
    for (int idx = threadIdx.x; idx < NK*CIN*9; idx += 256) {
        int k = idx / (CIN*9);
        int jj = idx - k * (CIN*9);
        s[k][jj] = wb[((size_t)k*COUT + co)*(CIN*9) + jj];
    }
    if (threadIdx.x < BB*NK) sa[threadIdx.x] = g_a[threadIdx.x];
    int ct = co >> 6, co_t = (co >> 4) & 3, r = co & 15;
    __syncthreads();
    for (int b = 0; b < BB; b++) {
        float a0 = sa[b*NK+0], a1 = sa[b*NK+1], a2 = sa[b*NK+2], a3 = sa[b*NK+3];
        for (int idx = threadIdx.x; idx < 9*CIN; idx += 256) {
            int tap = idx >> 8;
            int ci  = idx & 255;
            int src = ci*9 + tap;
            float v = a0*s[0][src] + a1*s[1][src] + a2*s[2][src] + a3*s[3][src];
            int dy = tap / 3, dx = tap - dy*3;
            int stage = ci >> 4, k_t = (ci >> 3) & 1, cc = ci & 7;
            int lane = (r & 7)*4 + (cc & 3);
            int vv   = ((r >> 3) & 1) + 2*((cc >> 2) & 1);
            size_t dst = ((((((((((size_t)b*4 + ct)*NSTG + stage)*3 + dy)*3 + dx)*4 + co_t)*2 + k_t)*32 + lane)*4)) + vv;
            g_wa[dst] = __uint_as_float(f2tf32(v));
        }
    }
}

// ===================== 4) conv: tf32 mma.sync, 3-taps-per-sync pipeline =====================
// grid (14 row-quads, 4 co-quarters, 32 b), 128 threads (4 warps), 3 CTAs/SM.
// Row-step = one filter row (dy, dx=0..2). 48 row-steps; ONE wait+sync per row-step.
// Per row-step issue: { A(next row-step, 12KB), 1/3 of sx(next stage) }.

#define SXB_BYTES  (6*58*64)                // 22272 per sx buffer
#define SAB_BYTES  12288                    // per A buffer (3 taps)
#define SX_SLOTS   (6*58*4)                 // 1392 16B slots per sx buffer
#define SX_CHUNK   (SX_SLOTS/3)             // 464 slots per row-step
#define SMEM_SZ    (2*SXB_BYTES + 2*SAB_BYTES)   // 69120 B

__global__ void __launch_bounds__(128, 3)
conv_kernel(float* __restrict__ out) {
    extern __shared__ float smem[];
    uint32_t sxaddr = smem_u32(smem);
    uint32_t saddrA = sxaddr + 2*SXB_BYTES;

    int tid = threadIdx.x, lane = tid & 31;
    int lane4 = lane & 3, laneq = lane >> 2;
    int nt4 = blockIdx.x, ct = blockIdx.y, b = blockIdx.z;
    int h0 = nt4 * NROWS;
    int orow = tid >> 5;                     // warp = output row 0..3

    uint32_t aLane = saddrA + (uint32_t)(lane * 16);
    const float* wabase = g_wa + (size_t)(b*4 + ct) * NSTG * 3 * (SAB_BYTES/4);

    float c[4][7][4];
    #pragma unroll
    for (int i = 0; i < 4; i++)
        #pragma unroll
        for (int j = 0; j < 7; j++)
            #pragma unroll
            for (int q = 0; q < 4; q++) c[i][j][q] = 0.f;

    // prologue: { sx(0) full, A(row-step 0) } in one group
    {
        const float4* xsrc = (const float4*)(g_xt + ((size_t)(b*NSTG + 0)*58 + h0) * (58*CIC));
        for (int u = tid; u < SX_SLOTS; u += 128)
            CP_ASYNC16(sxaddr + (uint32_t)(u*16), xsrc + u);
        const float* asrc = wabase;          // stage 0, dy 0
        #pragma unroll
        for (int it = 0; it < 6; it++) {
            int u = it*128 + tid;            // 0..767 float4 slots
            CP_ASYNC16(saddrA + (uint32_t)(u*16), asrc + u*4);
        }
        CP_COMMIT();
        CP_WAIT0();
        __syncthreads();
    }

    for (int s = 0; s < NSTG; s++) {
        #pragma unroll
        for (int r = 0; r < 3; r++) {
            int rs = s*3 + r;
            bool issue = (rs + 1 < NRS);
            // ---- issue async group: A(rs+1) + sx chunk r of stage s+1
            if (issue) {
                int rn = rs + 1;
                int sn = rn / 3, dyn = rn - sn*3;
                const float* asrc = wabase + (size_t)(sn*3 + dyn) * (SAB_BYTES/4);
                uint32_t adst = saddrA + (uint32_t)((rn & 1) * SAB_BYTES);
                #pragma unroll
                for (int it = 0; it < 6; it++) {
                    int u = it*128 + tid;
                    CP_ASYNC16(adst + (uint32_t)(u*16), asrc + u*4);
                }
                if (s + 1 < NSTG) {
                    const float4* xsrc = (const float4*)(g_xt + ((size_t)(b*NSTG + s+1)*58 + h0) * (58*CIC));
                    uint32_t xdst = sxaddr + (uint32_t)(((s+1) & 1) * SXB_BYTES);
                    #pragma unroll
                    for (int it = 0; it < 4; it++) {
                        int u = r*SX_CHUNK + it*128 + tid;
                        if (u < (r+1)*SX_CHUNK)
                            CP_ASYNC16(xdst + (uint32_t)(u*16), xsrc + u);
                    }
                }
                CP_COMMIT();
            }

            // ---- compute 3 taps: dy=r, dx=0..2
            uint32_t sAbase = aLane + (uint32_t)((rs & 1) * SAB_BYTES);
            #pragma unroll
            for (int dx = 0; dx < 3; dx++) {
                int hb = ((dx + laneq) & 2) << 4;    // XOR-swizzle half select
                uint32_t sxw = sxaddr + (uint32_t)((s & 1) * SXB_BYTES)
                             + (uint32_t)((((orow + r)*58 + dx + laneq) * 64) + lane4*8);
                uint32_t sxk0 = sxw + (uint32_t)hb;
                uint32_t sxk1 = sxw + (uint32_t)(32 ^ hb);
                #pragma unroll
                for (int kk = 0; kk < 2; kk++) {
                    uint32_t a[4][4];
                    #pragma unroll
                    for (int mt = 0; mt < 4; mt++)
                        LDSV4(a[mt][0], a[mt][1], a[mt][2], a[mt][3],
                              sAbase + (uint32_t)((dx*8 + mt*2 + kk)*512));
                    uint32_t bbase = kk ? sxk1 : sxk0;
                    #pragma unroll
                    for (int nt = 0; nt < 7; nt++) {
                        uint32_t bf[2];
                        LDSV2(bf[0], bf[1], bbase + (uint32_t)(nt*512));
                        mma_tf32(c[0][nt], a[0], bf);
                        mma_tf32(c[1][nt], a[1], bf);
                        mma_tf32(c[2][nt], a[2], bf);
                        mma_tf32(c[3][nt], a[3], bf);
                    }
                }
            }

            if (issue) {
                CP_WAIT0();
                __syncthreads();
            }
        }
    }

    // ---- epilogue: float2 stores
    int h = h0 + orow;
    #pragma unroll
    for (int mt = 0; mt < 4; mt++) {
        int co_base = ct*64 + mt*16 + laneq;
        #pragma unroll
        for (int half = 0; half < 2; half++) {
            int co = co_base + half*8;
            float* plane = out + ((size_t)(b*COUT + co)*HH + h)*WWD;
            #pragma unroll
            for (int nt = 0; nt < 7; nt++) {
                int wcol = nt*8 + lane4*2;
                *(float2*)(plane + wcol) = make_float2(c[mt][nt][half*2], c[mt][nt][half*2 + 1]);
            }
        }
    }
}

// ===================== launch =====================
extern "C" void kernel_launch(void* const* d_in, const int* in_sizes, int n_in,
                              void* d_out, int out_size) {
    const float* x    = (const float*)d_in[0];
    const float* wb   = (const float*)d_in[1];
    const float* fc1w = (const float*)d_in[2];
    const float* fc1b = (const float*)d_in[3];
    const float* fc2w = (const float*)d_in[4];
    const float* fc2b = (const float*)d_in[5];
    float* out = (float*)d_out;

    cudaFuncSetAttribute(conv_kernel, cudaFuncAttributeMaxDynamicSharedMemorySize, SMEM_SZ);
    cudaFuncSetAttribute(conv_kernel, cudaFuncAttributePreferredSharedMemoryCarveout,
                         cudaSharedmemCarveoutMaxShared);

    gap_kernel<<<BB*CIN, 256>>>(x);
    router_kernel<<<BB, 64>>>(fc1w, fc1b, fc2w, fc2b);
    xpose_kernel<<<dim3(58, NSTG, BB), 128>>>(x);
    mix_kernel<<<COUT, 256>>>(wb);
    conv_kernel<<<dim3(HH/NROWS, 4, BB), 128, SMEM_SZ>>>(out);
}

// round 15
// speedup vs baseline: 1.1183x; 1.0332x over previous
#include <cuda_runtime.h>
#include <cstdint>

#define BB   32
#define CIN  256
#define HH   56
#define WWD  56
#define COUT 256
#define NK   4
#define HID  64

#define CIC   16            // ci per stage
#define NSTG  (CIN/CIC)     // 16
#define NROWS 4             // output rows per CTA
#define NRS   (NSTG*3)      // 48 row-steps

// -------- scratch (device globals) --------
__device__ float g_v[BB*CIN];
__device__ float g_a[BB*NK];
// mixed weights (tf32), row-step grouped + fragment-permuted:
// [b][ct(4)][stage(16)][dy(3)][dx(3)][co_t(4)][kk(2)][lane(32)][v(4)]
__device__ __align__(16) float g_wa[(size_t)BB*9*COUT*CIN];
// pre-transposed x (tf32, halo-padded, ci-permuted, XOR-swizzled): [b][stage][hp(58)][iw(58)][16]
__device__ __align__(16) float g_xt[(size_t)BB*NSTG*58*58*CIC];

// ===================== helpers =====================
__device__ __forceinline__ uint32_t smem_u32(const void* p) {
    uint32_t a;
    asm("{ .reg .u64 t; cvta.to.shared.u64 t, %1; cvt.u32.u64 %0, t; }" : "=r"(a) : "l"(p));
    return a;
}
__device__ __forceinline__ uint32_t f2tf32(float f) {
    uint32_t r;
    asm("cvt.rna.tf32.f32 %0, %1;" : "=r"(r) : "f"(f));
    return r;
}
__device__ __forceinline__ void mma_tf32(float* c, const uint32_t* a, const uint32_t* b) {
    asm volatile("mma.sync.aligned.m16n8k8.row.col.f32.tf32.tf32.f32 "
        "{%0,%1,%2,%3}, {%4,%5,%6,%7}, {%8,%9}, {%0,%1,%2,%3};"
        : "+f"(c[0]), "+f"(c[1]), "+f"(c[2]), "+f"(c[3])
        : "r"(a[0]), "r"(a[1]), "r"(a[2]), "r"(a[3]), "r"(b[0]), "r"(b[1]));
}
#define CP_ASYNC16(dst, src) \
    asm volatile("cp.async.ca.shared.global [%0], [%1], 16;" :: "r"(dst), "l"(src) : "memory")
#define CP_COMMIT() asm volatile("cp.async.commit_group;" ::: "memory")
#define CP_WAIT0()  asm volatile("cp.async.wait_group 0;" ::: "memory")

#define LDSV4(r0,r1,r2,r3,a) \
    asm volatile("ld.shared.v4.u32 {%0,%1,%2,%3}, [%4];" : "=r"(r0),"=r"(r1),"=r"(r2),"=r"(r3) : "r"(a))
#define LDSV2(r0,r1,a) \
    asm volatile("ld.shared.v2.u32 {%0,%1}, [%2];" : "=r"(r0),"=r"(r1) : "r"(a))

// ===================== 1) global average pool (float4) =====================
__global__ void gap_kernel(const float* __restrict__ x) {
    int bc = blockIdx.x;
    const float4* p = (const float4*)(x + (size_t)bc * (HH*WWD));
    float s = 0.f;
    for (int i = threadIdx.x; i < (HH*WWD)/4; i += 256) {
        float4 v = p[i];
        s += (v.x + v.y) + (v.z + v.w);
    }
    __shared__ float red[256];
    red[threadIdx.x] = s;
    __syncthreads();
    for (int off = 128; off > 0; off >>= 1) {
        if (threadIdx.x < off) red[threadIdx.x] += red[threadIdx.x + off];
        __syncthreads();
    }
    if (threadIdx.x == 0) g_v[bc] = red[0] * (1.0f / (HH*WWD));
}

// ===================== 2) router MLP + softmax =====================
__global__ void router_kernel(const float* __restrict__ fc1w, const float* __restrict__ fc1b,
                              const float* __restrict__ fc2w, const float* __restrict__ fc2b) {
    int b = blockIdx.x;
    __shared__ float sv[CIN];
    __shared__ float sh[HID];
    __shared__ float sl[NK];
    for (int i = threadIdx.x; i < CIN; i += 64) sv[i] = g_v[b*CIN + i];
    __syncthreads();
    int j = threadIdx.x;
    float acc = fc1b[j];
    for (int c = 0; c < CIN; c++) acc += sv[c] * fc1w[j*CIN + c];
    sh[j] = acc > 0.f ? acc : 0.f;
    __syncthreads();
    if (j < NK) {
        float l = fc2b[j];
        for (int t = 0; t < HID; t++) l += sh[t] * fc2w[j*HID + t];
        sl[j] = l;
    }
    __syncthreads();
    if (j == 0) {
        float m = sl[0];
        for (int k = 1; k < NK; k++) m = fmaxf(m, sl[k]);
        float e[NK], ssum = 0.f;
        for (int k = 0; k < NK; k++) { e[k] = expf(sl[k] - m); ssum += e[k]; }
        float inv = 1.0f / ssum;
        for (int k = 0; k < NK; k++) g_a[b*NK + k] = e[k] * inv;
    }
}

// ===================== 3) merged aux: mix (blocks 0..255) + xpose (rest) =====================
// mix: one block per co; all 32 samples with banks held in smem (wb read ONCE).
// xpose: one block per (hp, stage, b); writes tf32/permuted/swizzled g_xt.
#define MIXB 256
__global__ void __launch_bounds__(256) aux_kernel(const float* __restrict__ x,
                                                  const float* __restrict__ wb) {
    __shared__ float s[NK][CIN*9];
    __shared__ float sa[BB*NK];
    int tid = threadIdx.x;

    if (blockIdx.x < MIXB) {
        // ---------------- mix body ----------------
        int co = blockIdx.x;
        for (int idx = tid; idx < NK*CIN*9; idx += 256) {
            int k = idx / (CIN*9);
            int jj = idx - k * (CIN*9);
            s[k][jj] = wb[((size_t)k*COUT + co)*(CIN*9) + jj];
        }
        if (tid < BB*NK) sa[tid] = g_a[tid];
        int ct = co >> 6, co_t = (co >> 4) & 3, r = co & 15;
        __syncthreads();
        for (int b = 0; b < BB; b++) {
            float a0 = sa[b*NK+0], a1 = sa[b*NK+1], a2 = sa[b*NK+2], a3 = sa[b*NK+3];
            for (int idx = tid; idx < 9*CIN; idx += 256) {
                int tap = idx >> 8;
                int ci  = idx & 255;
                int src = ci*9 + tap;
                float v = a0*s[0][src] + a1*s[1][src] + a2*s[2][src] + a3*s[3][src];
                int dy = tap / 3, dx = tap - dy*3;
                int stage = ci >> 4, k_t = (ci >> 3) & 1, cc = ci & 7;
                int lane = (r & 7)*4 + (cc & 3);
                int vv   = ((r >> 3) & 1) + 2*((cc >> 2) & 1);
                size_t dst = ((((((((((size_t)b*4 + ct)*NSTG + stage)*3 + dy)*3 + dx)*4 + co_t)*2 + k_t)*32 + lane)*4)) + vv;
                g_wa[dst] = __uint_as_float(f2tf32(v));
            }
        }
    } else {
        // ---------------- xpose body ----------------
        int bi = blockIdx.x - MIXB;
        int hp = bi % 58;
        int rest = bi / 58;
        int sg = rest % NSTG;
        int b  = rest / NSTG;
        float* orow = g_xt + ((size_t)(b*NSTG + sg)*58 + hp) * (58*CIC);
        if (hp == 0 || hp == 57) {
            for (int u = tid; u < 58*CIC; u += 256) orow[u] = 0.f;
            return;
        }
        float (*tile)[57] = reinterpret_cast<float(*)[57]>(&s[0][0]);
        int h = hp - 1;
        for (int u = tid; u < CIC*WWD; u += 256) {
            int ci = u / WWD, w = u - ci*WWD;
            tile[ci][w] = x[((size_t)(b*CIN + sg*CIC + ci)*HH + h)*WWD + w];
        }
        __syncthreads();
        for (int u = tid; u < 58*CIC; u += 256) {
            int iw = u >> 4, pp = u & 15;
            float v = 0.f;
            if (iw >= 1 && iw <= 56) {
                int ci = (pp & 8) | ((pp & 1) << 2) | ((pp >> 1) & 3);   // inverse perm
                v = tile[ci][iw - 1];
            }
            // XOR swizzle: halves of the 16-word group swapped for iw with bit1 set
            orow[(iw << 4) | (pp ^ ((iw & 2) << 2))] = __uint_as_float(f2tf32(v));
        }
    }
}

// ===================== 4) conv: tf32 mma.sync, 3-taps-per-sync pipeline =====================
// grid (14 row-quads, 4 co-quarters, 32 b), 128 threads (4 warps), 3 CTAs/SM.
// Row-step = one filter row (dy, dx=0..2). 48 row-steps; ONE wait+sync per row-step.
// Per row-step issue: { A(next row-step, 12KB), 1/3 of sx(next stage) }.

#define SXB_BYTES  (6*58*64)                // 22272 per sx buffer
#define SAB_BYTES  12288                    // per A buffer (3 taps)
#define SX_SLOTS   (6*58*4)                 // 1392 16B slots per sx buffer
#define SX_CHUNK   (SX_SLOTS/3)             // 464 slots per row-step
#define SMEM_SZ    (2*SXB_BYTES + 2*SAB_BYTES)   // 69120 B

__global__ void __launch_bounds__(128, 3)
conv_kernel(float* __restrict__ out) {
    extern __shared__ float smem[];
    uint32_t sxaddr = smem_u32(smem);
    uint32_t saddrA = sxaddr + 2*SXB_BYTES;

    int tid = threadIdx.x, lane = tid & 31;
    int lane4 = lane & 3, laneq = lane >> 2;
    int nt4 = blockIdx.x, ct = blockIdx.y, b = blockIdx.z;
    int h0 = nt4 * NROWS;
    int orow = tid >> 5;                     // warp = output row 0..3

    uint32_t aLane = saddrA + (uint32_t)(lane * 16);
    const float* wabase = g_wa + (size_t)(b*4 + ct) * NSTG * 3 * (SAB_BYTES/4);

    float c[4][7][4];
    #pragma unroll
    for (int i = 0; i < 4; i++)
        #pragma unroll
        for (int j = 0; j < 7; j++)
            #pragma unroll
            for (int q = 0; q < 4; q++) c[i][j][q] = 0.f;

    // prologue: { sx(0) full, A(row-step 0) } in one group
    {
        const float4* xsrc = (const float4*)(g_xt + ((size_t)(b*NSTG + 0)*58 + h0) * (58*CIC));
        for (int u = tid; u < SX_SLOTS; u += 128)
            CP_ASYNC16(sxaddr + (uint32_t)(u*16), xsrc + u);
        const float* asrc = wabase;          // stage 0, dy 0
        #pragma unroll
        for (int it = 0; it < 6; it++) {
            int u = it*128 + tid;            // 0..767 float4 slots
            CP_ASYNC16(saddrA + (uint32_t)(u*16), asrc + u*4);
        }
        CP_COMMIT();
        CP_WAIT0();
        __syncthreads();
    }

    for (int s = 0; s < NSTG; s++) {
        #pragma unroll
        for (int r = 0; r < 3; r++) {
            int rs = s*3 + r;
            bool issue = (rs + 1 < NRS);
            // ---- issue async group: A(rs+1) + sx chunk r of stage s+1
            if (issue) {
                int rn = rs + 1;
                int sn = rn / 3, dyn = rn - sn*3;
                const float* asrc = wabase + (size_t)(sn*3 + dyn) * (SAB_BYTES/4);
                uint32_t adst = saddrA + (uint32_t)((rn & 1) * SAB_BYTES);
                #pragma unroll
                for (int it = 0; it < 6; it++) {
                    int u = it*128 + tid;
                    CP_ASYNC16(adst + (uint32_t)(u*16), asrc + u*4);
                }
                if (s + 1 < NSTG) {
                    const float4* xsrc = (const float4*)(g_xt + ((size_t)(b*NSTG + s+1)*58 + h0) * (58*CIC));
                    uint32_t xdst = sxaddr + (uint32_t)(((s+1) & 1) * SXB_BYTES);
                    #pragma unroll
                    for (int it = 0; it < 4; it++) {
                        int u = r*SX_CHUNK + it*128 + tid;
                        if (u < (r+1)*SX_CHUNK)
                            CP_ASYNC16(xdst + (uint32_t)(u*16), xsrc + u);
                    }
                }
                CP_COMMIT();
            }

            // ---- compute 3 taps: dy=r, dx=0..2
            uint32_t sAbase = aLane + (uint32_t)((rs & 1) * SAB_BYTES);
            #pragma unroll
            for (int dx = 0; dx < 3; dx++) {
                int hb = ((dx + laneq) & 2) << 4;    // XOR-swizzle half select
                uint32_t sxw = sxaddr + (uint32_t)((s & 1) * SXB_BYTES)
                             + (uint32_t)((((orow + r)*58 + dx + laneq) * 64) + lane4*8);
                uint32_t sxk0 = sxw + (uint32_t)hb;
                uint32_t sxk1 = sxw + (uint32_t)(32 ^ hb);
                #pragma unroll
                for (int kk = 0; kk < 2; kk++) {
                    uint32_t a[4][4];
                    #pragma unroll
                    for (int mt = 0; mt < 4; mt++)
                        LDSV4(a[mt][0], a[mt][1], a[mt][2], a[mt][3],
                              sAbase + (uint32_t)((dx*8 + mt*2 + kk)*512));
                    uint32_t bbase = kk ? sxk1 : sxk0;
                    #pragma unroll
                    for (int nt = 0; nt < 7; nt++) {
                        uint32_t bf[2];
                        LDSV2(bf[0], bf[1], bbase + (uint32_t)(nt*512));
                        mma_tf32(c[0][nt], a[0], bf);
                        mma_tf32(c[1][nt], a[1], bf);
                        mma_tf32(c[2][nt], a[2], bf);
                        mma_tf32(c[3][nt], a[3], bf);
                    }
                }
            }

            if (issue) {
                CP_WAIT0();
                __syncthreads();
            }
        }
    }

    // ---- epilogue: float2 stores
    int h = h0 + orow;
    #pragma unroll
    for (int mt = 0; mt < 4; mt++) {
        int co_base = ct*64 + mt*16 + laneq;
        #pragma unroll
        for (int half = 0; half < 2; half++) {
            int co = co_base + half*8;
            float* plane = out + ((size_t)(b*COUT + co)*HH + h)*WWD;
            #pragma unroll
            for (int nt = 0; nt < 7; nt++) {
                int wcol = nt*8 + lane4*2;
                *(float2*)(plane + wcol) = make_float2(c[mt][nt][half*2], c[mt][nt][half*2 + 1]);
            }
        }
    }
}

// ===================== launch =====================
extern "C" void kernel_launch(void* const* d_in, const int* in_sizes, int n_in,
                              void* d_out, int out_size) {
    const float* x    = (const float*)d_in[0];
    const float* wb   = (const float*)d_in[1];
    const float* fc1w = (const float*)d_in[2];
    const float* fc1b = (const float*)d_in[3];
    const float* fc2w = (const float*)d_in[4];
    const float* fc2b = (const float*)d_in[5];
    float* out = (float*)d_out;

    cudaFuncSetAttribute(conv_kernel, cudaFuncAttributeMaxDynamicSharedMemorySize, SMEM_SZ);
    cudaFuncSetAttribute(conv_kernel, cudaFuncAttributePreferredSharedMemoryCarveout,
                         cudaSharedmemCarveoutMaxShared);

    gap_kernel<<<BB*CIN, 256>>>(x);
    router_kernel<<<BB, 64>>>(fc1w, fc1b, fc2w, fc2b);
    aux_kernel<<<MIXB + 58*NSTG*BB, 256>>>(x, wb);
    conv_kernel<<<dim3(HH/NROWS, 4, BB), 128, SMEM_SZ>>>(out);
}